// round 8
// baseline (speedup 1.0000x reference)
#include <cuda_runtime.h>
#include <cstdint>
#include <math.h>

#define EPSV 1e-4f
#define NM   3249                    // 57*57 floats per matrix
#define GM   4                       // matrices per tile
#define TILE_FLOATS (GM * NM)        // 12996
#define TILE_BYTES  (TILE_FLOATS * 4)// 51984 (multiple of 16)
#define NTILES 2048
#define NBLK   296                   // 148 SMs * 2 blocks

// Scratch (allocation-free). Counter reset by last arriver -> graph-replay safe.
__device__ float g_a[128 * 64 * 3];
__device__ int   g_cnt[128];

// Shared layout (floats)
#define SM_BUF_OFF  0                // 2 * 12996 = 25992
#define SM_PQ_OFF   25992            // float2[57] = 114
#define SM_W23_OFF  26106            // 40
#define SM_C_OFF    26146            // 684 (also scan scratch: needs 260)
#define SM_LAST_OFF 26830            // flag
#define SM_MBAR_OFF 26832            // 2 mbarriers, 16B (26832*4 % 8 == 0)
#define SM_FLOATS   26836
#define SM_BYTES    (SM_FLOATS * 4)  // 107344 B -> 2 blocks/SM

__device__ __forceinline__ void mbar_init(unsigned int mbar, unsigned int cnt) {
    asm volatile("mbarrier.init.shared.b64 [%0], %1;" :: "r"(mbar), "r"(cnt) : "memory");
}
__device__ __forceinline__ void mbar_expect_tx(unsigned int mbar, unsigned int bytes) {
    asm volatile("mbarrier.arrive.expect_tx.shared.b64 _, [%0], %1;"
                 :: "r"(mbar), "r"(bytes) : "memory");
}
__device__ __forceinline__ void bulk_copy_g2s(unsigned int sdst, const void* gsrc,
                                              unsigned int bytes, unsigned int mbar) {
    asm volatile("cp.async.bulk.shared::cta.global.mbarrier::complete_tx::bytes "
                 "[%0], [%1], %2, [%3];"
                 :: "r"(sdst), "l"(gsrc), "r"(bytes), "r"(mbar) : "memory");
}
__device__ __forceinline__ void mbar_wait_parity(unsigned int mbar, unsigned int parity) {
    asm volatile(
        "{\n\t"
        ".reg .pred P1;\n\t"
        "WAIT_LOOP_%=:\n\t"
        "mbarrier.try_wait.parity.acquire.cta.shared::cta.b64 P1, [%0], %1, 0x989680;\n\t"
        "@P1 bra.uni WAIT_DONE_%=;\n\t"
        "bra.uni WAIT_LOOP_%=;\n\t"
        "WAIT_DONE_%=:\n\t"
        "}"
        :: "r"(mbar), "r"(parity) : "memory");
}

// Scan + head for batch b. Called by ALL threads of the block (internal barrier).
// Uses sm_c (684 floats) as scratch.
__device__ void scan_batch(int b, float* sm_c,
                           const float* __restrict__ lin_w,
                           const float* __restrict__ lin_b,
                           const float* __restrict__ alpha,
                           float* __restrict__ out) {
    float* a0 = sm_c;
    float* a1 = sm_c + 64;
    float* a2 = sm_c + 128;
    float* lw = sm_c + 192;  // 51
    float* lb = sm_c + 243;  // 17
    int tid = threadIdx.x;
    __threadfence();         // acquire side of the counter handshake
    if (tid < 64) {
        const float* ab = g_a + ((size_t)b * 64 + tid) * 3;
        a0[tid] = ab[0]; a1[tid] = ab[1]; a2[tid] = ab[2];
    }
    if (tid < 51) lw[tid] = lin_w[tid];
    if (tid < 17) lb[tid] = lin_b[tid];
    __syncthreads();
    if (tid >= 64) return;

    const int t = tid;
    float s  = 1.f / (1.f + expf(-alpha[0]));
    float os = 1.f - s;

    float h00 = 0.f, h01 = 0.f, h11 = 0.f;
    for (int k = 0; k <= t; k++) {
        float mean = 0.5f * (h00 + h11);
        float diff = 0.5f * (h00 - h11);
        float rad  = sqrtf(diff * diff + h01 * h01);
        float r00, r01, r11;
        if (rad > 1e-20f) {
            float l1 = mean + rad, l2 = mean - rad;
            float m1 = fmaxf(l1, EPSV), m2 = fmaxf(l2, EPSV);
            float c1 = (m1 - m2) / (l1 - l2);
            float c0 = m1 - c1 * l1;
            r00 = c1 * h00 + c0;
            r01 = c1 * h01;
            r11 = c1 * h11 + c0;
        } else {
            if (mean >= EPSV) { r00 = h00; r01 = h01; r11 = h11; }
            else              { r00 = EPSV; r01 = 0.f; r11 = EPSV; }
        }
        h00 = fmaf(s, a0[k], os * r00);
        h01 = fmaf(s, a1[k], os * r01);
        h11 = fmaf(s, a2[k], os * r11);
    }

    float mean = 0.5f * (h00 + h11);
    float diff = 0.5f * (h00 - h11);
    float rad  = sqrtf(diff * diff + h01 * h01);
    float l1 = mean + rad, l2 = mean - rad;
    float d  = l1 - l2;
    float c1 = (d > 0.f) ? (log1pf(d / l2) / d) : (1.f / l1);
    float c0 = logf(l2) - c1 * l2;
    float v0 = c1 * h00 + c0;
    float v1 = c1 * h01;
    float v2 = c1 * h11 + c0;

    float* o = out + ((size_t)b * 64 + t) * 17;
    #pragma unroll
    for (int j = 0; j < 17; j++)
        o[j] = fmaf(lw[j * 3], v0, fmaf(lw[j * 3 + 1], v1, fmaf(lw[j * 3 + 2], v2, lb[j])));
}

__global__ void __launch_bounds__(512, 2)
fused_kernel(const float* __restrict__ x,
             const float* __restrict__ W1,
             const float* __restrict__ W2,
             const float* __restrict__ W3,
             const float* __restrict__ lin_w,
             const float* __restrict__ lin_b,
             const float* __restrict__ alpha,
             float* __restrict__ out) {
    extern __shared__ float sm[];
    float2* sm_pq  = (float2*)(sm + SM_PQ_OFF);
    float*  sm_w23 = sm + SM_W23_OFF;
    float*  sm_c   = sm + SM_C_OFF;
    int*    sm_last = (int*)(sm + SM_LAST_OFF);

    const int tid = threadIdx.x;
    const int blk = blockIdx.x;

    unsigned int sbase;
    asm("{ .reg .u64 t; cvta.to.shared.u64 t, %1; cvt.u32.u64 %0, t; }"
        : "=r"(sbase) : "l"(sm));
    const unsigned int mbar0 = sbase + SM_MBAR_OFF * 4u;
    const unsigned int mbar1 = mbar0 + 8u;

    // --- Init: mbarriers (tid 0) and W2@W3 (tids 1..80, disjoint) ---
    if (tid == 0) { mbar_init(mbar0, 1); mbar_init(mbar1, 1); }
    if (tid >= 64 && tid < 104) {
        int v = tid - 64;
        int j = v >> 1, u = v & 1;
        float s = 0.f;
        #pragma unroll
        for (int k = 0; k < 10; k++) s = fmaf(__ldg(W2 + j * 10 + k), __ldg(W3 + k * 2 + u), s);
        sm_w23[v] = s;
    }
    __syncthreads();

    // --- Prologue: kick off the first TMA; compute P meanwhile ---
    if (tid == 0 && blk < NTILES) {
        mbar_expect_tx(mbar0, TILE_BYTES);
        bulk_copy_g2s(sbase, x + (size_t)blk * TILE_FLOATS, TILE_BYTES, mbar0);
    }
    if (tid < 114) {
        int i = tid >> 1, u = tid & 1;
        float s = 0.f;
        #pragma unroll
        for (int j = 0; j < 20; j++) s = fmaf(__ldg(W1 + i * 20 + j), sm_w23[j * 2 + u], s);
        ((float*)&sm_pq[i])[u] = s;
    }
    __syncthreads();

    // --- Persistent pipelined loop over tiles blk, blk+296, ... ---
    int ph0 = 0, ph1 = 0;
    int ibuf = 0;
    for (int t = blk; t < NTILES; t += NBLK, ibuf ^= 1) {
        // Prefetch next tile into the other buffer (it is free: compute on it
        // finished last iteration, enforced by the trailing __syncthreads).
        int nxt = t + NBLK;
        if (tid == 0 && nxt < NTILES) {
            unsigned int mb_n  = ibuf ? mbar0 : mbar1;
            unsigned int off_n = ibuf ? 0u : (unsigned)TILE_BYTES;
            mbar_expect_tx(mb_n, TILE_BYTES);
            bulk_copy_g2s(sbase + off_n, x + (size_t)nxt * TILE_FLOATS, TILE_BYTES, mb_n);
        }

        // Wait for current buffer (acquire)
        if (ibuf) { mbar_wait_parity(mbar1, ph1); ph1 ^= 1; }
        else      { mbar_wait_parity(mbar0, ph0); ph0 ^= 1; }

        // Compute: thread r < 228 owns row r of the 4 staged matrices
        const float* sx = sm + (ibuf ? TILE_FLOATS : 0);
        if (tid < 228) {
            const float* xr = sx + tid * 57;
            float y0 = 0.f, y1 = 0.f;
            #pragma unroll
            for (int k = 0; k < 57; k++) {
                float  vv = xr[k];
                float2 p  = sm_pq[k];            // warp-uniform broadcast
                y0 = fmaf(vv, p.x, y0);
                y1 = fmaf(vv, p.y, y1);
            }
            int m = tid / 57;
            float2 pi = sm_pq[tid - 57 * m];
            sm_c[tid * 3 + 0] = pi.x * y0;
            sm_c[tid * 3 + 1] = pi.x * y1;
            sm_c[tid * 3 + 2] = pi.y * y1;
        }
        __syncthreads();

        // Finalize + publish
        if (tid < 12) {
            int m = tid / 3, comp = tid - 3 * m;
            const float* base = sm_c + (m * 57) * 3 + comp;
            float s = 0.f;
            #pragma unroll
            for (int r = 0; r < 57; r++) s += base[r * 3];
            g_a[(size_t)(GM * t + m) * 3 + comp] = s;
            __threadfence();                     // release writes before counter
        }
        __syncthreads();

        const int b = t >> 4;                    // 16 tiles per batch b
        if (tid == 0) {
            int old = atomicAdd(&g_cnt[b], 1);
            *sm_last = (old == 15);
            if (old == 15) g_cnt[b] = 0;         // reset for graph replay
        }
        __syncthreads();
        if (*sm_last) {
            scan_batch(b, sm_c, lin_w, lin_b, alpha, out);
        }
        __syncthreads();                         // sm_c & buffers free for next iter
    }
}

// ---------------------------------------------------------------------------
extern "C" void kernel_launch(void* const* d_in, const int* in_sizes, int n_in,
                              void* d_out, int out_size) {
    const float* x     = (const float*)d_in[0];  // (128,64,57,57)
    const float* W1    = (const float*)d_in[1];  // (57,20)
    const float* W2    = (const float*)d_in[2];  // (20,10)
    const float* W3    = (const float*)d_in[3];  // (10,2)
    const float* lin_w = (const float*)d_in[4];  // (17,3)
    const float* lin_b = (const float*)d_in[5];  // (17,)
    const float* alpha = (const float*)d_in[6];  // (1,)
    float* out = (float*)d_out;                  // (128,64,17)

    cudaFuncSetAttribute(fused_kernel, cudaFuncAttributeMaxDynamicSharedMemorySize, SM_BYTES);
    fused_kernel<<<NBLK, 512, SM_BYTES>>>(x, W1, W2, W3, lin_w, lin_b, alpha, out);
}

// round 9
// speedup vs baseline: 2.3982x; 2.3982x over previous
#include <cuda_runtime.h>
#include <cstdint>
#include <math.h>

#define EPSV 1e-4f
#define NM   3249                    // 57*57 floats per matrix
#define GM   4                       // matrices per block
#define TILE_BYTES (GM * NM * 4)     // 51984 = 9 * 5776, each piece 16B-multiple
#define NPIECE 9
#define PIECE  5776

// Scratch (allocation-free). Counter reset by last arriver -> graph-replay safe.
__device__ float g_a[128 * 64 * 3];
__device__ int   g_cnt[128];

// Shared layout (floats)
#define SM_X_OFF    0        // 12996: 4 staged matrices
#define SM_PQ_OFF   12996    // float2[57] = 114 floats
#define SM_W23_OFF  13110    // 40
#define SM_C_OFF    13150    // 228*3 per-row partials = 684
#define SM_LAST_OFF 13834    // int flag
#define SM_MBAR_OFF 13836    // 8B mbarrier (13836*4 % 8 == 0)
#define SM_FLOATS   13840
#define SM_BYTES    (SM_FLOATS * 4)

__device__ __forceinline__ void mbar_init(unsigned int mbar, unsigned int cnt) {
    asm volatile("mbarrier.init.shared.b64 [%0], %1;" :: "r"(mbar), "r"(cnt) : "memory");
}
__device__ __forceinline__ void mbar_expect_tx(unsigned int mbar, unsigned int bytes) {
    asm volatile("mbarrier.arrive.expect_tx.shared.b64 _, [%0], %1;"
                 :: "r"(mbar), "r"(bytes) : "memory");
}
__device__ __forceinline__ void bulk_copy_g2s(unsigned int sdst, const void* gsrc,
                                              unsigned int bytes, unsigned int mbar) {
    asm volatile("cp.async.bulk.shared::cta.global.mbarrier::complete_tx::bytes "
                 "[%0], [%1], %2, [%3];"
                 :: "r"(sdst), "l"(gsrc), "r"(bytes), "r"(mbar) : "memory");
}
__device__ __forceinline__ void mbar_wait_parity(unsigned int mbar, unsigned int parity) {
    asm volatile(
        "{\n\t"
        ".reg .pred P1;\n\t"
        "WAIT_LOOP_%=:\n\t"
        "mbarrier.try_wait.parity.acquire.cta.shared::cta.b64 P1, [%0], %1, 0x989680;\n\t"
        "@P1 bra.uni WAIT_DONE_%=;\n\t"
        "bra.uni WAIT_LOOP_%=;\n\t"
        "WAIT_DONE_%=:\n\t"
        "}"
        :: "r"(mbar), "r"(parity) : "memory");
}

__global__ void __launch_bounds__(512, 4)
fused_kernel(const float* __restrict__ x,
             const float* __restrict__ W1,
             const float* __restrict__ W2,
             const float* __restrict__ W3,
             const float* __restrict__ lin_w,
             const float* __restrict__ lin_b,
             const float* __restrict__ alpha,
             float* __restrict__ out) {
    extern __shared__ float sm[];
    float*  sm_x   = sm + SM_X_OFF;
    float2* sm_pq  = (float2*)(sm + SM_PQ_OFF);
    float*  sm_w23 = sm + SM_W23_OFF;
    float*  sm_c   = sm + SM_C_OFF;
    int*    sm_last = (int*)(sm + SM_LAST_OFF);

    const int tid = threadIdx.x;
    const int blk = blockIdx.x;                 // 2048 blocks, 4 matrices each
    const char* xg = (const char*)(x + (size_t)blk * (GM * NM));

    unsigned int sbase;
    asm("{ .reg .u64 t; cvta.to.shared.u64 t, %1; cvt.u32.u64 %0, t; }"
        : "=r"(sbase) : "l"(sm));
    const unsigned int sx_addr   = sbase + SM_X_OFF * 4u;
    const unsigned int mbar_addr = sbase + SM_MBAR_OFF * 4u;

    // --- mbarrier init, then 9 concurrent bulk copies covering the 52KB tile ---
    if (tid == 0) mbar_init(mbar_addr, 1);
    __syncthreads();
    if (tid == 0) {
        mbar_expect_tx(mbar_addr, TILE_BYTES);
        #pragma unroll
        for (int c = 0; c < NPIECE; c++)
            bulk_copy_g2s(sx_addr + c * PIECE, xg + c * PIECE, PIECE, mbar_addr);
    }

    // --- P = W1@W2@W3 (hidden under the in-flight copies) ---
    if (tid < 40) {
        int j = tid >> 1, u = tid & 1;
        float s = 0.f;
        #pragma unroll
        for (int k = 0; k < 10; k++) s = fmaf(__ldg(W2 + j * 10 + k), __ldg(W3 + k * 2 + u), s);
        sm_w23[tid] = s;
    }
    __syncthreads();
    if (tid < 114) {
        int i = tid >> 1, u = tid & 1;
        float s = 0.f;
        #pragma unroll
        for (int j = 0; j < 20; j++) s = fmaf(__ldg(W1 + i * 20 + j), sm_w23[j * 2 + u], s);
        ((float*)&sm_pq[i])[u] = s;
    }

    // --- Wait for the tile (HW-sleep try_wait), phase 0 ---
    mbar_wait_parity(mbar_addr, 0);
    __syncthreads();

    // --- Compute: thread t owns global row t (addr = t*57 + k), bank stride 25 ---
    if (tid < 228) {
        const float* xr = sm_x + tid * 57;
        float y0 = 0.f, y1 = 0.f;
        #pragma unroll
        for (int k = 0; k < 57; k++) {
            float  vv = xr[k];
            float2 p  = sm_pq[k];                // warp-uniform broadcast
            y0 = fmaf(vv, p.x, y0);
            y1 = fmaf(vv, p.y, y1);
        }
        int m = tid / 57;
        float2 pi = sm_pq[tid - 57 * m];
        sm_c[tid * 3 + 0] = pi.x * y0;
        sm_c[tid * 3 + 1] = pi.x * y1;
        sm_c[tid * 3 + 2] = pi.y * y1;
    }
    __syncthreads();

    // --- Finalize: 12 threads each sum 57 partials for (matrix m, component c) ---
    if (tid < 12) {
        int m = tid / 3;
        int comp = tid - 3 * m;
        const float* base = sm_c + (m * 57) * 3 + comp;
        float s = 0.f;
        #pragma unroll
        for (int r = 0; r < 57; r++) s += base[r * 3];
        g_a[(size_t)(GM * blk + m) * 3 + comp] = s;
    }
    __threadfence();
    __syncthreads();

    const int b = blk >> 4;                      // 16 blocks per b
    if (tid == 0) {
        int old = atomicAdd(&g_cnt[b], 1);
        *sm_last = (old == 15);
        if (old == 15) g_cnt[b] = 0;             // reset for graph replay
    }
    __syncthreads();
    if (!*sm_last) return;

    // --- Scan phase (only last-arriving block per b) ---
    __threadfence();                             // acquire
    float* a0 = sm_x;                            // reuse staged region
    float* a1 = sm_x + 64;
    float* a2 = sm_x + 128;
    float* lw = sm_x + 192;                      // 51
    float* lb = sm_x + 243;                      // 17
    if (tid < 64) {
        const float* ab = g_a + ((size_t)b * 64 + tid) * 3;
        a0[tid] = ab[0]; a1[tid] = ab[1]; a2[tid] = ab[2];
    }
    if (tid < 51) lw[tid] = lin_w[tid];
    if (tid < 17) lb[tid] = lin_b[tid];
    __syncthreads();
    if (tid >= 64) return;

    const int t = tid;
    float s  = 1.f / (1.f + expf(-alpha[0]));
    float os = 1.f - s;

    float h00 = 0.f, h01 = 0.f, h11 = 0.f;
    for (int k = 0; k <= t; k++) {
        float mean = 0.5f * (h00 + h11);
        float diff = 0.5f * (h00 - h11);
        float rad  = sqrtf(diff * diff + h01 * h01);
        float r00, r01, r11;
        if (rad > 1e-20f) {
            float l1 = mean + rad, l2 = mean - rad;
            float m1 = fmaxf(l1, EPSV), m2 = fmaxf(l2, EPSV);
            float c1 = (m1 - m2) / (l1 - l2);
            float c0 = m1 - c1 * l1;
            r00 = c1 * h00 + c0;
            r01 = c1 * h01;
            r11 = c1 * h11 + c0;
        } else {
            if (mean >= EPSV) { r00 = h00; r01 = h01; r11 = h11; }
            else              { r00 = EPSV; r01 = 0.f; r11 = EPSV; }
        }
        h00 = fmaf(s, a0[k], os * r00);
        h01 = fmaf(s, a1[k], os * r01);
        h11 = fmaf(s, a2[k], os * r11);
    }

    float mean = 0.5f * (h00 + h11);
    float diff = 0.5f * (h00 - h11);
    float rad  = sqrtf(diff * diff + h01 * h01);
    float l1 = mean + rad, l2 = mean - rad;
    float d  = l1 - l2;
    float c1 = (d > 0.f) ? (log1pf(d / l2) / d) : (1.f / l1);
    float c0 = logf(l2) - c1 * l2;
    float v0 = c1 * h00 + c0;
    float v1 = c1 * h01;
    float v2 = c1 * h11 + c0;

    float* o = out + ((size_t)b * 64 + t) * 17;
    #pragma unroll
    for (int j = 0; j < 17; j++)
        o[j] = fmaf(lw[j * 3], v0, fmaf(lw[j * 3 + 1], v1, fmaf(lw[j * 3 + 2], v2, lb[j])));
}

// ---------------------------------------------------------------------------
extern "C" void kernel_launch(void* const* d_in, const int* in_sizes, int n_in,
                              void* d_out, int out_size) {
    const float* x     = (const float*)d_in[0];  // (128,64,57,57)
    const float* W1    = (const float*)d_in[1];  // (57,20)
    const float* W2    = (const float*)d_in[2];  // (20,10)
    const float* W3    = (const float*)d_in[3];  // (10,2)
    const float* lin_w = (const float*)d_in[4];  // (17,3)
    const float* lin_b = (const float*)d_in[5];  // (17,)
    const float* alpha = (const float*)d_in[6];  // (1,)
    float* out = (float*)d_out;                  // (128,64,17)

    cudaFuncSetAttribute(fused_kernel, cudaFuncAttributeMaxDynamicSharedMemorySize, SM_BYTES);
    fused_kernel<<<2048, 512, SM_BYTES>>>(x, W1, W2, W3, lin_w, lin_b, alpha, out);
}